// round 7
// baseline (speedup 1.0000x reference)
#include <cuda_runtime.h>
#include <cuda_fp16.h>
#include <cstdint>

// GAT layer, N=8192, Fin=128, Fout=64.
// inputs: x [N,128] f32, adj [N,N] f32 (0/1), W [128,64] f32, a [128,1] f32
// output: [N,64] f32

#define N      8192
#define FOUT   64
#define TI     128
#define TJ     32
#define JSPLIT 16
#define JRANGE (N / JSPLIT)     // 512
#define NT     (JRANGE / TJ)    // 16

#define ADJ_STR 36              // floats per adj smem row (144 B)
#define WH_STR  72              // halves per Wh smem row (144 B)
#define STAGE_ADJ_B (TI * ADJ_STR * 4)   // 18432
#define STAGE_WH_B  (TJ * WH_STR * 2)    //  4608
#define STAGE_B     (STAGE_ADJ_B + STAGE_WH_B)  // 23040
#define NSTAGE 4
#define SMEMB_BYTES (NSTAGE * STAGE_B)   // 92160

// ---------------- device scratch ----------------
__device__ float2 g_E1P[N];                  // (e^Wh1, e^{0.2 Wh1}) fp32
__device__ __half g_E2XH[N];                 // fp16 e^Wh2
__device__ __half g_E2YH[N];                 // fp16 e^{0.2 Wh2}
__device__ __half g_Wh_h[N * FOUT];          // Wh [j][f] fp16
__device__ float  g_acc[JSPLIT][N * FOUT];   // partial numerators [js][i][f]
__device__ float  g_den[JSPLIT][N];          // partial denominators

// ---------------- helpers ----------------
__device__ __forceinline__ unsigned long long packdup(float v) {
    unsigned long long r;
    asm("mov.b64 %0, {%1, %1};" : "=l"(r) : "f"(v));
    return r;
}
__device__ __forceinline__ float2 unpack2(unsigned long long v) {
    float2 r;
    asm("mov.b64 {%0, %1}, %2;" : "=f"(r.x), "=f"(r.y) : "l"(v));
    return r;
}
#define FFMA2(d, a, b) asm("fma.rn.f32x2 %0, %1, %2, %3;" : "=l"(d) : "l"(a), "l"(b), "l"(d))

#define CP_ASYNC16(dst, src) \
    asm volatile("cp.async.cg.shared.global [%0], [%1], 16;" :: "r"(dst), "l"(src))
#define CP_COMMIT() asm volatile("cp.async.commit_group;")
#define CP_WAIT2()  asm volatile("cp.async.wait_group 2;" ::: "memory")

#define LDSM_X4_T(d0, d1, d2, d3, addr)                                        \
    asm volatile("ldmatrix.sync.aligned.m8n8.x4.trans.shared.b16 "             \
                 "{%0,%1,%2,%3}, [%4];"                                        \
                 : "=r"(d0), "=r"(d1), "=r"(d2), "=r"(d3) : "r"(addr))

#define MMA_F16(D, A, B0, B1)                                                 \
    asm("mma.sync.aligned.m16n8k16.row.col.f32.f16.f16.f32 "                  \
        "{%0,%1,%2,%3},{%4,%5,%6,%7},{%8,%9},{%0,%1,%2,%3};"                  \
        : "+f"((D)[0]), "+f"((D)[1]), "+f"((D)[2]), "+f"((D)[3])              \
        : "r"((A)[0]), "r"((A)[1]), "r"((A)[2]), "r"((A)[3]),                 \
          "r"(B0), "r"(B1))

// ============================================================
// Kernel A: Wh = x@W, attention dots, exp tables (fp16), Wh fp16 [j][f].
// 128 blocks x 512 threads; 64 rows/block, 8 threads/row.
// ============================================================
#define XSTR 132
#define PREP_SMEM ((8192 + 64 * XSTR + 128) * 4)

__global__ void __launch_bounds__(512) gat_prep(const float* __restrict__ x,
                                                const float* __restrict__ W,
                                                const float* __restrict__ a)
{
    extern __shared__ float psm[];
    float* wS = psm;                  // [128][64]
    float* xS = psm + 8192;           // [64][XSTR]
    float* aS = psm + 8192 + 64 * XSTR;

    const int t = threadIdx.x;
    const int row0 = blockIdx.x * 64;

    #pragma unroll
    for (int q = 0; q < 4; q++) {
        int idx = (q * 512 + t) * 4;
        *(float4*)&wS[idx] = *(const float4*)&W[idx];
    }
    const float* xb = x + (size_t)row0 * 128;
    #pragma unroll
    for (int q = 0; q < 4; q++) {
        int flat = (q * 512 + t) * 4;
        int r = flat >> 7, c = flat & 127;
        *(float4*)&xS[r * XSTR + c] = *(const float4*)&xb[flat];
    }
    if (t < 32) *(float4*)&aS[t * 4] = *(const float4*)&a[t * 4];
    __syncthreads();

    const int r = t >> 3, c = t & 7;
    unsigned long long acc4[4] = {0ull, 0ull, 0ull, 0ull};

    #pragma unroll 8
    for (int kk = 0; kk < 128; kk++) {
        unsigned long long xd = packdup(xS[r * XSTR + kk]);
        const unsigned long long* w =
            reinterpret_cast<const unsigned long long*>(&wS[kk * 64]);
        FFMA2(acc4[0], xd, w[c]);
        FFMA2(acc4[1], xd, w[8 + c]);
        FFMA2(acc4[2], xd, w[16 + c]);
        FFMA2(acc4[3], xd, w[24 + c]);
    }

    float p1 = 0.f, p2 = 0.f;
    const int row = row0 + r;
    #pragma unroll
    for (int m = 0; m < 4; m++) {
        float2 u = unpack2(acc4[m]);
        const int col = 16 * m + 2 * c;
        p1 += u.x * aS[col]      + u.y * aS[col + 1];
        p2 += u.x * aS[64 + col] + u.y * aS[64 + col + 1];
        *(__half2*)&g_Wh_h[(size_t)row * 64 + col] = __floats2half2_rn(u.x, u.y);
    }
    p1 += __shfl_xor_sync(0xffffffffu, p1, 1);
    p1 += __shfl_xor_sync(0xffffffffu, p1, 2);
    p1 += __shfl_xor_sync(0xffffffffu, p1, 4);
    p2 += __shfl_xor_sync(0xffffffffu, p2, 1);
    p2 += __shfl_xor_sync(0xffffffffu, p2, 2);
    p2 += __shfl_xor_sync(0xffffffffu, p2, 4);

    if (c == 0) {
        g_E1P[row]  = make_float2(__expf(p1), __expf(0.2f * p1));
        g_E2XH[row] = __float2half(__expf(p2));
        g_E2YH[row] = __float2half(__expf(0.2f * p2));
    }
}

// ============================================================
// Kernel B: f-split warps. grid (64, 16) x 256 threads (8 warps).
// Warp w: i-rows [iw*32, +32) (iw = w&3), f-half fw = w>>2 (32 cols).
// Per warp/tile: 4 LDSM.x4 + A-build + 16 MMAs (+2 den MMAs if fw==0).
// 4-stage cp.async ring, 1 barrier/tile.
// ============================================================
__global__ void __launch_bounds__(256, 2) gat_attn(const float* __restrict__ adj)
{
    extern __shared__ char smem[];
    const int t = threadIdx.x, lane = t & 31, warp = t >> 5;
    const int iw = warp & 3, fw = warp >> 2;
    const int ib = blockIdx.x, js = blockIdx.y;
    const int i_base = ib * TI, i_warp = i_base + iw * 32;
    const int j0 = js * JRANGE;
    const int r0 = lane >> 2, c0 = (lane & 3) * 2;

    const uint32_t sb = (uint32_t)__cvta_generic_to_shared(smem);

    // adj staging map: 256 threads, 64B each (row t&127, chunks (t>>7)*4 ..+3)
    const int arow = t & 127, acb = (t >> 7) * 4;
    const float* adjp = adj + (size_t)(i_base + arow) * N + j0 + acb * 4;
    // Wh staging map: 256 threads, 16B each
    const int wrow = t >> 3, wseg = t & 7;
    const __half* wsrc = g_Wh_h + (size_t)(j0 + wrow) * 64 + wseg * 8;

    // e1 fp16 splats (invariant)
    __half2 e1x2[2][2], e1y2[2][2];
    #pragma unroll
    for (int mt = 0; mt < 2; mt++)
        #pragma unroll
        for (int aa = 0; aa < 2; aa++) {
            float2 e1f = g_E1P[i_warp + mt * 16 + aa * 8 + r0];
            e1x2[mt][aa] = __half2half2(__float2half(e1f.x));
            e1y2[mt][aa] = __half2half2(__float2half(e1f.y));
        }

    float acc[2][4][4];
    float accden[2][4];
    #pragma unroll
    for (int mt = 0; mt < 2; mt++) {
        #pragma unroll
        for (int nt = 0; nt < 4; nt++)
            #pragma unroll
            for (int e = 0; e < 4; e++) acc[mt][nt][e] = 0.f;
        #pragma unroll
        for (int e = 0; e < 4; e++) accden[mt][e] = 0.f;
    }
    const uint32_t bones = (r0 == 0) ? 0x3C003C00u : 0u;   // fp16 ones column

    // ldmatrix lane map (x4.trans)
    const int mm = lane >> 3;
    const int ldsm_row = (mm & 1) * 8 + (lane & 7);
    const int ldsm_f   = mm >> 1;

#define PREFETCH(tt)                                                           \
    do {                                                                       \
        const int s_ = (tt) & 3;                                               \
        const uint32_t ab_ = sb + s_ * STAGE_B + arow * (ADJ_STR * 4);         \
        const float* as_ = adjp + (tt) * TJ;                                   \
        CP_ASYNC16(ab_ + (acb + 0) * 16, as_ + 0);                             \
        CP_ASYNC16(ab_ + (acb + 1) * 16, as_ + 4);                             \
        CP_ASYNC16(ab_ + (acb + 2) * 16, as_ + 8);                             \
        CP_ASYNC16(ab_ + (acb + 3) * 16, as_ + 12);                            \
        CP_ASYNC16(sb + s_ * STAGE_B + STAGE_ADJ_B + wrow * (WH_STR * 2)       \
                       + wseg * 16, wsrc + (tt) * TJ * 64);                    \
        CP_COMMIT();                                                           \
    } while (0)

    PREFETCH(0); PREFETCH(1); PREFETCH(2);

    #pragma unroll 1
    for (int it = 0; it < NT; it++) {
        const int s = it & 3;
        const int jt = j0 + it * TJ;
        CP_WAIT2();
        __syncthreads();
        if (it + 3 < NT) { PREFETCH(it + 3); } else { CP_COMMIT(); }

        const uint32_t wb = sb + s * STAGE_B + STAGE_ADJ_B;
        const float* adjS = (const float*)(smem + s * STAGE_B);

        // ---- B fragments (f-half fw) via ldmatrix.x4.trans ----
        uint32_t b[4][2][2];
        #pragma unroll
        for (int kt = 0; kt < 2; kt++) {
            const uint32_t abase = wb + (kt * 16 + ldsm_row) * (WH_STR * 2)
                                      + fw * 64 + ldsm_f * 16;
            #pragma unroll
            for (int p = 0; p < 2; p++) {
                uint32_t q0, q1, q2, q3;
                LDSM_X4_T(q0, q1, q2, q3, abase + p * 32);
                b[2 * p][kt][0] = q0; b[2 * p][kt][1] = q1;
                b[2 * p + 1][kt][0] = q2; b[2 * p + 1][kt][1] = q3;
            }
        }

        // ---- e2 fp16 pair loads (L1-hot) ----
        __half2 ex2[2][2], ey2[2][2];
        #pragma unroll
        for (int kt = 0; kt < 2; kt++)
            #pragma unroll
            for (int hh = 0; hh < 2; hh++) {
                const int jj = jt + kt * 16 + hh * 8 + c0;
                ex2[kt][hh] = *(const __half2*)&g_E2XH[jj];
                ey2[kt][hh] = *(const __half2*)&g_E2YH[jj];
            }

        // ---- A fragments (P) in half2 ----
        uint32_t afr[2][2][4];
        #pragma unroll
        for (int mt = 0; mt < 2; mt++)
            #pragma unroll
            for (int kt = 0; kt < 2; kt++)
                #pragma unroll
                for (int aa = 0; aa < 2; aa++) {
                    const int R = iw * 32 + mt * 16 + aa * 8 + r0;
                    #pragma unroll
                    for (int hh = 0; hh < 2; hh++) {
                        float2 ad = *(const float2*)&adjS[R * ADJ_STR + kt * 16 + hh * 8 + c0];
                        __half2 ah = __floats2half2_rn(ad.x, ad.y);
                        __half2 u  = __hmul2(e1x2[mt][aa], ex2[kt][hh]);
                        __half2 v  = __hmul2(e1y2[mt][aa], ey2[kt][hh]);
                        __half2 p  = __hmul2(__hmax2(u, v), ah);
                        afr[mt][kt][aa + 2 * hh] = *(uint32_t*)&p;
                    }
                }

        // ---- MMAs ----
        #pragma unroll
        for (int mt = 0; mt < 2; mt++) {
            #pragma unroll
            for (int nt = 0; nt < 4; nt++) {
                MMA_F16(acc[mt][nt], afr[mt][0], b[nt][0][0], b[nt][0][1]);
                MMA_F16(acc[mt][nt], afr[mt][1], b[nt][1][0], b[nt][1][1]);
            }
            if (fw == 0) {
                MMA_F16(accden[mt], afr[mt][0], bones, bones);
                MMA_F16(accden[mt], afr[mt][1], bones, bones);
            }
        }
    }

    // ---- epilogue ----
    float* ob = g_acc[js];
    #pragma unroll
    for (int mt = 0; mt < 2; mt++) {
        const int ir = i_warp + mt * 16 + r0;
        #pragma unroll
        for (int nt = 0; nt < 4; nt++) {
            const int fc = fw * 32 + nt * 8 + c0;
            *(float2*)&ob[(size_t)ir * FOUT + fc] =
                make_float2(acc[mt][nt][0], acc[mt][nt][1]);
            *(float2*)&ob[(size_t)(ir + 8) * FOUT + fc] =
                make_float2(acc[mt][nt][2], acc[mt][nt][3]);
        }
    }
    if (fw == 0 && (lane & 3) == 0) {
        #pragma unroll
        for (int mt = 0; mt < 2; mt++) {
            g_den[js][i_warp + mt * 16 + r0]     = accden[mt][0];
            g_den[js][i_warp + mt * 16 + 8 + r0] = accden[mt][2];
        }
    }
}

// ============================================================
// Kernel C: combine partials, normalize, ELU.
// ============================================================
__global__ void __launch_bounds__(256) gat_final(float* __restrict__ out)
{
    const int idx = blockIdx.x * 256 + threadIdx.x;   // < N*FOUT
    const int i = idx >> 6;
    float d = 0.f, v = 0.f;
    #pragma unroll
    for (int s = 0; s < JSPLIT; s++) {
        d += g_den[s][i];
        v += g_acc[s][idx];
    }
    float h = v / d;
    out[idx] = (h > 0.f) ? h : expm1f(h);
}

// ============================================================
extern "C" void kernel_launch(void* const* d_in, const int* in_sizes, int n_in,
                              void* d_out, int out_size)
{
    const float* x   = (const float*)d_in[0];
    const float* adj = (const float*)d_in[1];
    const float* W   = (const float*)d_in[2];
    const float* a   = (const float*)d_in[3];
    float* out = (float*)d_out;

    cudaFuncSetAttribute(gat_prep, cudaFuncAttributeMaxDynamicSharedMemorySize,
                         PREP_SMEM);
    cudaFuncSetAttribute(gat_attn, cudaFuncAttributeMaxDynamicSharedMemorySize,
                         SMEMB_BYTES);

    gat_prep<<<N / 64, 512, PREP_SMEM>>>(x, W, a);
    gat_attn<<<dim3(N / TI, JSPLIT), 256, SMEMB_BYTES>>>(adj);
    gat_final<<<(N * FOUT) / 256, 256>>>(out);
}

// round 8
// speedup vs baseline: 1.4683x; 1.4683x over previous
#include <cuda_runtime.h>
#include <cuda_fp16.h>
#include <cstdint>

// GAT layer, N=8192, Fin=128, Fout=64.
// inputs: x [N,128] f32, adj [N,N] f32 (0/1), W [128,64] f32, a [128,1] f32
// output: [N,64] f32

#define N      8192
#define FOUT   64
#define TI     128
#define TJ     32
#define JSPLIT 16
#define JRANGE (N / JSPLIT)     // 512
#define NT     (JRANGE / TJ)    // 16

#define WH_STR 72                        // halves per Wh smem row (144 B)
#define STAGE_WH_B (TJ * WH_STR * 2)     // 4608
#define SMEMB_BYTES (4 * STAGE_WH_B)     // 18432

// ---------------- device scratch ----------------
__device__ float2 g_E1P[N];                  // (e^Wh1, e^{0.2 Wh1}) fp32
__device__ __half g_E2XH[N];                 // fp16 e^Wh2
__device__ __half g_E2YH[N];                 // fp16 e^{0.2 Wh2}
__device__ __half g_Wh_h[N * FOUT];          // Wh [j][f] fp16
__device__ float  g_acc[JSPLIT][N * FOUT];   // partial numerators [js][i][f]
__device__ float  g_den[JSPLIT][N];          // partial denominators

// ---------------- helpers ----------------
__device__ __forceinline__ unsigned long long packdup(float v) {
    unsigned long long r;
    asm("mov.b64 %0, {%1, %1};" : "=l"(r) : "f"(v));
    return r;
}
__device__ __forceinline__ float2 unpack2(unsigned long long v) {
    float2 r;
    asm("mov.b64 {%0, %1}, %2;" : "=f"(r.x), "=f"(r.y) : "l"(v));
    return r;
}
#define FFMA2(d, a, b) asm("fma.rn.f32x2 %0, %1, %2, %3;" : "=l"(d) : "l"(a), "l"(b), "l"(d))

#define CP_ASYNC16(dst, src) \
    asm volatile("cp.async.cg.shared.global [%0], [%1], 16;" :: "r"(dst), "l"(src))
#define CP_COMMIT() asm volatile("cp.async.commit_group;")
#define CP_WAIT2()  asm volatile("cp.async.wait_group 2;" ::: "memory")

#define LDSM_X4_T(d0, d1, d2, d3, addr)                                        \
    asm volatile("ldmatrix.sync.aligned.m8n8.x4.trans.shared.b16 "             \
                 "{%0,%1,%2,%3}, [%4];"                                        \
                 : "=r"(d0), "=r"(d1), "=r"(d2), "=r"(d3) : "r"(addr))

#define MMA_F16(D, A, B0, B1)                                                 \
    asm("mma.sync.aligned.m16n8k16.row.col.f32.f16.f16.f32 "                  \
        "{%0,%1,%2,%3},{%4,%5,%6,%7},{%8,%9},{%0,%1,%2,%3};"                  \
        : "+f"((D)[0]), "+f"((D)[1]), "+f"((D)[2]), "+f"((D)[3])              \
        : "r"((A)[0]), "r"((A)[1]), "r"((A)[2]), "r"((A)[3]),                 \
          "r"(B0), "r"(B1))

// ============================================================
// Kernel A: Wh = x@W, attention dots, exp tables (fp16), Wh fp16 [j][f].
// 256 blocks x 256 threads; 32 rows/block, 8 threads/row.
// Dyn smem: wS f32[8192] | xS f32[32*132] | aS f32[128] = 50176 B
// ============================================================
#define XSTR 132
#define PREP_SMEM ((8192 + 32 * XSTR + 128) * 4)

__global__ void __launch_bounds__(256) gat_prep(const float* __restrict__ x,
                                                const float* __restrict__ W,
                                                const float* __restrict__ a)
{
    extern __shared__ float psm[];
    float* wS = psm;                    // [128][64]
    float* xS = psm + 8192;             // [32][XSTR]
    float* aS = psm + 8192 + 32 * XSTR;

    const int t = threadIdx.x;
    const int row0 = blockIdx.x * 32;

    #pragma unroll
    for (int q = 0; q < 8; q++) {
        int idx = (q * 256 + t) * 4;
        *(float4*)&wS[idx] = *(const float4*)&W[idx];
    }
    const float* xb = x + (size_t)row0 * 128;
    #pragma unroll
    for (int q = 0; q < 4; q++) {
        int flat = (q * 256 + t) * 4;
        int r = flat >> 7, c = flat & 127;
        *(float4*)&xS[r * XSTR + c] = *(const float4*)&xb[flat];
    }
    if (t < 32) *(float4*)&aS[t * 4] = *(const float4*)&a[t * 4];
    __syncthreads();

    const int r = t >> 3, c = t & 7;
    unsigned long long acc4[4] = {0ull, 0ull, 0ull, 0ull};

    #pragma unroll 8
    for (int kk = 0; kk < 128; kk++) {
        unsigned long long xd = packdup(xS[r * XSTR + kk]);
        const unsigned long long* w =
            reinterpret_cast<const unsigned long long*>(&wS[kk * 64]);
        FFMA2(acc4[0], xd, w[c]);
        FFMA2(acc4[1], xd, w[8 + c]);
        FFMA2(acc4[2], xd, w[16 + c]);
        FFMA2(acc4[3], xd, w[24 + c]);
    }

    float p1 = 0.f, p2 = 0.f;
    const int row = row0 + r;
    #pragma unroll
    for (int m = 0; m < 4; m++) {
        float2 u = unpack2(acc4[m]);
        const int col = 16 * m + 2 * c;
        p1 += u.x * aS[col]      + u.y * aS[col + 1];
        p2 += u.x * aS[64 + col] + u.y * aS[64 + col + 1];
        *(__half2*)&g_Wh_h[(size_t)row * 64 + col] = __floats2half2_rn(u.x, u.y);
    }
    p1 += __shfl_xor_sync(0xffffffffu, p1, 1);
    p1 += __shfl_xor_sync(0xffffffffu, p1, 2);
    p1 += __shfl_xor_sync(0xffffffffu, p1, 4);
    p2 += __shfl_xor_sync(0xffffffffu, p2, 1);
    p2 += __shfl_xor_sync(0xffffffffu, p2, 2);
    p2 += __shfl_xor_sync(0xffffffffu, p2, 4);

    if (c == 0) {
        g_E1P[row]  = make_float2(__expf(p1), __expf(0.2f * p1));
        g_E2XH[row] = __float2half(__expf(p2));
        g_E2YH[row] = __float2half(__expf(0.2f * p2));
    }
}

// ============================================================
// Kernel B: adj direct-to-register + fp16 MMA; smem = Wh ring only.
// grid (64, 16) x 128 threads (4 warps), 3 blocks/SM.
// Warp w: i-rows [w*32, +32), all 64 f. 34 MMAs/warp/tile.
// ============================================================
__global__ void __launch_bounds__(128, 3) gat_attn(const float* __restrict__ adj)
{
    extern __shared__ char smem[];            // 4-stage Wh ring
    const int t = threadIdx.x, lane = t & 31, warp = t >> 5;
    const int ib = blockIdx.x, js = blockIdx.y;
    const int i_base = ib * TI, i_warp = i_base + warp * 32;
    const int j0 = js * JRANGE;
    const int r0 = lane >> 2, c0 = (lane & 3) * 2;

    const uint32_t sb = (uint32_t)__cvta_generic_to_shared(smem);

    // Wh staging: 256 16B-chunks per stage, 2 per thread (chunks t, t+128)
    const int wrow0 = t >> 3,         wseg0 = t & 7;
    const int wrow1 = (t + 128) >> 3, wseg1 = t & 7;

#define PREFETCH_WH(tt)                                                        \
    do {                                                                       \
        const uint32_t wb_ = sb + ((tt) & 3) * STAGE_WH_B;                     \
        CP_ASYNC16(wb_ + wrow0 * 144 + wseg0 * 16,                             \
                   g_Wh_h + (size_t)(j0 + (tt) * TJ + wrow0) * 64 + wseg0 * 8);\
        CP_ASYNC16(wb_ + wrow1 * 144 + wseg1 * 16,                             \
                   g_Wh_h + (size_t)(j0 + (tt) * TJ + wrow1) * 64 + wseg1 * 8);\
        CP_COMMIT();                                                           \
    } while (0)

    // adj row pointers for this thread's fragment rows
    const float* rp[2][2];
    #pragma unroll
    for (int mt = 0; mt < 2; mt++)
        #pragma unroll
        for (int aa = 0; aa < 2; aa++)
            rp[mt][aa] = adj + (size_t)(i_warp + mt * 16 + aa * 8 + r0) * N + j0 + c0;

    float2 ab[16];   // raw adj prefetch buffer: [mt][kt][aa][hh]
#define LOAD_ADJ(tt)                                                           \
    do {                                                                       \
        const int off_ = (tt) * TJ;                                            \
        _Pragma("unroll")                                                      \
        for (int mt_ = 0; mt_ < 2; mt_++)                                      \
            _Pragma("unroll")                                                  \
            for (int kt_ = 0; kt_ < 2; kt_++)                                  \
                _Pragma("unroll")                                              \
                for (int aa_ = 0; aa_ < 2; aa_++)                              \
                    _Pragma("unroll")                                          \
                    for (int hh_ = 0; hh_ < 2; hh_++)                          \
                        ab[mt_ * 8 + kt_ * 4 + aa_ * 2 + hh_] =                \
                            *(const float2*)(rp[mt_][aa_] + off_ +             \
                                             kt_ * 16 + hh_ * 8);              \
    } while (0)

    // e1 fp16 splats (invariant)
    __half2 e1x2[2][2], e1y2[2][2];
    #pragma unroll
    for (int mt = 0; mt < 2; mt++)
        #pragma unroll
        for (int aa = 0; aa < 2; aa++) {
            float2 e1f = g_E1P[i_warp + mt * 16 + aa * 8 + r0];
            e1x2[mt][aa] = __half2half2(__float2half(e1f.x));
            e1y2[mt][aa] = __half2half2(__float2half(e1f.y));
        }

    float acc[2][8][4];
    float accden[2][4];
    #pragma unroll
    for (int mt = 0; mt < 2; mt++) {
        #pragma unroll
        for (int nt = 0; nt < 8; nt++)
            #pragma unroll
            for (int e = 0; e < 4; e++) acc[mt][nt][e] = 0.f;
        #pragma unroll
        for (int e = 0; e < 4; e++) accden[mt][e] = 0.f;
    }
    const uint32_t bones = (r0 == 0) ? 0x3C003C00u : 0u;   // fp16 ones column

    // ldmatrix lane map (x4.trans)
    const int mm = lane >> 3;
    const int ldsm_row = (mm & 1) * 8 + (lane & 7);
    const int ldsm_f   = mm >> 1;

    LOAD_ADJ(0);
    PREFETCH_WH(0); PREFETCH_WH(1); PREFETCH_WH(2);

    #pragma unroll 1
    for (int it = 0; it < NT; it++) {
        const int jt = j0 + it * TJ;
        CP_WAIT2();
        __syncthreads();
        if (it + 3 < NT) { PREFETCH_WH(it + 3); } else { CP_COMMIT(); }

        // ---- e2 fp16 pair loads (L1-hot) ----
        __half2 ex2[2][2], ey2[2][2];
        #pragma unroll
        for (int kt = 0; kt < 2; kt++)
            #pragma unroll
            for (int hh = 0; hh < 2; hh++) {
                const int jj = jt + kt * 16 + hh * 8 + c0;
                ex2[kt][hh] = *(const __half2*)&g_E2XH[jj];
                ey2[kt][hh] = *(const __half2*)&g_E2YH[jj];
            }

        // ---- A fragments (P) from register adj ----
        uint32_t afr[2][2][4];
        #pragma unroll
        for (int mt = 0; mt < 2; mt++)
            #pragma unroll
            for (int kt = 0; kt < 2; kt++)
                #pragma unroll
                for (int aa = 0; aa < 2; aa++)
                    #pragma unroll
                    for (int hh = 0; hh < 2; hh++) {
                        float2 ad = ab[mt * 8 + kt * 4 + aa * 2 + hh];
                        __half2 ah = __floats2half2_rn(ad.x, ad.y);
                        __half2 u  = __hmul2(e1x2[mt][aa], ex2[kt][hh]);
                        __half2 v  = __hmul2(e1y2[mt][aa], ey2[kt][hh]);
                        __half2 p  = __hmul2(__hmax2(u, v), ah);
                        afr[mt][kt][aa + 2 * hh] = *(uint32_t*)&p;
                    }

        // ---- reissue adj loads for next tile (hidden behind MMAs) ----
        if (it + 1 < NT) LOAD_ADJ(it + 1);

        // ---- MMAs with inline LDSM B fragments ----
        const uint32_t wb = sb + (it & 3) * STAGE_WH_B;
        #pragma unroll
        for (int kt = 0; kt < 2; kt++) {
            const uint32_t abase = wb + (kt * 16 + ldsm_row) * 144 + ldsm_f * 16;
            #pragma unroll
            for (int p = 0; p < 4; p++) {
                uint32_t q0, q1, q2, q3;
                LDSM_X4_T(q0, q1, q2, q3, abase + p * 32);
                uint32_t A0[4] = {afr[0][kt][0], afr[0][kt][1], afr[0][kt][2], afr[0][kt][3]};
                uint32_t A1[4] = {afr[1][kt][0], afr[1][kt][1], afr[1][kt][2], afr[1][kt][3]};
                MMA_F16(acc[0][2 * p],     A0, q0, q1);
                MMA_F16(acc[0][2 * p + 1], A0, q2, q3);
                MMA_F16(acc[1][2 * p],     A1, q0, q1);
                MMA_F16(acc[1][2 * p + 1], A1, q2, q3);
            }
            MMA_F16(accden[0], afr[0][kt], bones, bones);
            MMA_F16(accden[1], afr[1][kt], bones, bones);
        }
    }

    // ---- epilogue ----
    float* ob = g_acc[js];
    #pragma unroll
    for (int mt = 0; mt < 2; mt++) {
        const int ir = i_warp + mt * 16 + r0;
        #pragma unroll
        for (int nt = 0; nt < 8; nt++) {
            const int fc = nt * 8 + c0;
            *(float2*)&ob[(size_t)ir * FOUT + fc] =
                make_float2(acc[mt][nt][0], acc[mt][nt][1]);
            *(float2*)&ob[(size_t)(ir + 8) * FOUT + fc] =
                make_float2(acc[mt][nt][2], acc[mt][nt][3]);
        }
    }
    if ((lane & 3) == 0) {
        #pragma unroll
        for (int mt = 0; mt < 2; mt++) {
            g_den[js][i_warp + mt * 16 + r0]     = accden[mt][0];
            g_den[js][i_warp + mt * 16 + 8 + r0] = accden[mt][2];
        }
    }
}

// ============================================================
// Kernel C: combine partials, normalize, ELU.
// ============================================================
__global__ void __launch_bounds__(256) gat_final(float* __restrict__ out)
{
    const int idx = blockIdx.x * 256 + threadIdx.x;   // < N*FOUT
    const int i = idx >> 6;
    float d = 0.f, v = 0.f;
    #pragma unroll
    for (int s = 0; s < JSPLIT; s++) {
        d += g_den[s][i];
        v += g_acc[s][idx];
    }
    float h = v / d;
    out[idx] = (h > 0.f) ? h : expm1f(h);
}

// ============================================================
extern "C" void kernel_launch(void* const* d_in, const int* in_sizes, int n_in,
                              void* d_out, int out_size)
{
    const float* x   = (const float*)d_in[0];
    const float* adj = (const float*)d_in[1];
    const float* W   = (const float*)d_in[2];
    const float* a   = (const float*)d_in[3];
    float* out = (float*)d_out;

    cudaFuncSetAttribute(gat_prep, cudaFuncAttributeMaxDynamicSharedMemorySize,
                         PREP_SMEM);
    cudaFuncSetAttribute(gat_attn, cudaFuncAttributeMaxDynamicSharedMemorySize,
                         SMEMB_BYTES);

    gat_prep<<<N / 32, 256, PREP_SMEM>>>(x, W, a);
    gat_attn<<<dim3(N / TI, JSPLIT), TI, SMEMB_BYTES>>>(adj);
    gat_final<<<(N * FOUT) / 256, 256>>>(out);
}

// round 9
// speedup vs baseline: 1.4891x; 1.0142x over previous
#include <cuda_runtime.h>
#include <cuda_fp16.h>
#include <cstdint>

// GAT layer, N=8192, Fin=128, Fout=64.
// inputs: x [N,128] f32, adj [N,N] f32 (0/1), W [128,64] f32, a [128,1] f32
// output: [N,64] f32

#define N      8192
#define FOUT   64
#define TI     128
#define TJ     32
#define JSPLIT 16
#define JRANGE (N / JSPLIT)     // 512
#define NT     (JRANGE / TJ)    // 16

#define ADJ_STR 40                        // floats per adj smem row (160 B, conflict-free)
#define WH_STR  72                        // halves per Wh smem row (144 B)
#define STAGE_ADJ_B (TI * ADJ_STR * 4)    // 20480
#define STAGE_WH_B  (TJ * WH_STR * 2)     // 4608
#define STAGE_B     (STAGE_ADJ_B + STAGE_WH_B)   // 25088
#define NSTAGE 3
#define SMEMB_BYTES (NSTAGE * STAGE_B)    // 75264

// ---------------- device scratch ----------------
__device__ float2 g_E1P[N];                  // (e^Wh1, e^{0.2 Wh1}) fp32
__device__ __half g_E2XH[N];                 // fp16 e^Wh2
__device__ __half g_E2YH[N];                 // fp16 e^{0.2 Wh2}
__device__ __half g_Wh_h[N * FOUT];          // Wh [j][f] fp16
__device__ float  g_acc[JSPLIT][N * FOUT];   // partial numerators [js][i][f]
__device__ float  g_den[JSPLIT][N];          // partial denominators

// ---------------- helpers ----------------
__device__ __forceinline__ unsigned long long packdup(float v) {
    unsigned long long r;
    asm("mov.b64 %0, {%1, %1};" : "=l"(r) : "f"(v));
    return r;
}
__device__ __forceinline__ float2 unpack2(unsigned long long v) {
    float2 r;
    asm("mov.b64 {%0, %1}, %2;" : "=f"(r.x), "=f"(r.y) : "l"(v));
    return r;
}
#define FFMA2(d, a, b) asm("fma.rn.f32x2 %0, %1, %2, %3;" : "=l"(d) : "l"(a), "l"(b), "l"(d))

#define CP_ASYNC16(dst, src) \
    asm volatile("cp.async.cg.shared.global [%0], [%1], 16;" :: "r"(dst), "l"(src))
#define CP_COMMIT() asm volatile("cp.async.commit_group;")
#define CP_WAIT2()  asm volatile("cp.async.wait_group 2;" ::: "memory")

#define LDSM_X4_T(d0, d1, d2, d3, addr)                                        \
    asm volatile("ldmatrix.sync.aligned.m8n8.x4.trans.shared.b16 "             \
                 "{%0,%1,%2,%3}, [%4];"                                        \
                 : "=r"(d0), "=r"(d1), "=r"(d2), "=r"(d3) : "r"(addr))

#define MMA_F16(D, A, B0, B1)                                                 \
    asm("mma.sync.aligned.m16n8k16.row.col.f32.f16.f16.f32 "                  \
        "{%0,%1,%2,%3},{%4,%5,%6,%7},{%8,%9},{%0,%1,%2,%3};"                  \
        : "+f"((D)[0]), "+f"((D)[1]), "+f"((D)[2]), "+f"((D)[3])              \
        : "r"((A)[0]), "r"((A)[1]), "r"((A)[2]), "r"((A)[3]),                 \
          "r"(B0), "r"(B1))

// ============================================================
// Kernel A: Wh = x@W, attention dots, exp tables (fp16), Wh fp16 [j][f].
// 256 blocks x 256 threads; 32 rows/block, 8 threads/row.
// ============================================================
#define XSTR 132
#define PREP_SMEM ((8192 + 32 * XSTR + 128) * 4)

__global__ void __launch_bounds__(256) gat_prep(const float* __restrict__ x,
                                                const float* __restrict__ W,
                                                const float* __restrict__ a)
{
    extern __shared__ float psm[];
    float* wS = psm;                    // [128][64]
    float* xS = psm + 8192;             // [32][XSTR]
    float* aS = psm + 8192 + 32 * XSTR;

    const int t = threadIdx.x;
    const int row0 = blockIdx.x * 32;

    #pragma unroll
    for (int q = 0; q < 8; q++) {
        int idx = (q * 256 + t) * 4;
        *(float4*)&wS[idx] = *(const float4*)&W[idx];
    }
    const float* xb = x + (size_t)row0 * 128;
    #pragma unroll
    for (int q = 0; q < 4; q++) {
        int flat = (q * 256 + t) * 4;
        int r = flat >> 7, c = flat & 127;
        *(float4*)&xS[r * XSTR + c] = *(const float4*)&xb[flat];
    }
    if (t < 32) *(float4*)&aS[t * 4] = *(const float4*)&a[t * 4];
    __syncthreads();

    const int r = t >> 3, c = t & 7;
    unsigned long long acc4[4] = {0ull, 0ull, 0ull, 0ull};

    #pragma unroll 8
    for (int kk = 0; kk < 128; kk++) {
        unsigned long long xd = packdup(xS[r * XSTR + kk]);
        const unsigned long long* w =
            reinterpret_cast<const unsigned long long*>(&wS[kk * 64]);
        FFMA2(acc4[0], xd, w[c]);
        FFMA2(acc4[1], xd, w[8 + c]);
        FFMA2(acc4[2], xd, w[16 + c]);
        FFMA2(acc4[3], xd, w[24 + c]);
    }

    float p1 = 0.f, p2 = 0.f;
    const int row = row0 + r;
    #pragma unroll
    for (int m = 0; m < 4; m++) {
        float2 u = unpack2(acc4[m]);
        const int col = 16 * m + 2 * c;
        p1 += u.x * aS[col]      + u.y * aS[col + 1];
        p2 += u.x * aS[64 + col] + u.y * aS[64 + col + 1];
        *(__half2*)&g_Wh_h[(size_t)row * 64 + col] = __floats2half2_rn(u.x, u.y);
    }
    p1 += __shfl_xor_sync(0xffffffffu, p1, 1);
    p1 += __shfl_xor_sync(0xffffffffu, p1, 2);
    p1 += __shfl_xor_sync(0xffffffffu, p1, 4);
    p2 += __shfl_xor_sync(0xffffffffu, p2, 1);
    p2 += __shfl_xor_sync(0xffffffffu, p2, 2);
    p2 += __shfl_xor_sync(0xffffffffu, p2, 4);

    if (c == 0) {
        g_E1P[row]  = make_float2(__expf(p1), __expf(0.2f * p1));
        g_E2XH[row] = __float2half(__expf(p2));
        g_E2YH[row] = __float2half(__expf(0.2f * p2));
    }
}

// ============================================================
// Kernel B: 3-stage cp.async ring (adj+Wh) + fp16 MMA.
// grid (64, 16) x 128 threads (4 warps), 3 blocks/SM.
// Per tile: wait+sync -> A-build(LDS)+LDSM(to regs) -> sync ->
//           prefetch it+3 -> 34 MMAs.
// ============================================================
__global__ void __launch_bounds__(128, 3) gat_attn(const float* __restrict__ adj)
{
    extern __shared__ char smem[];
    const int t = threadIdx.x, lane = t & 31, warp = t >> 5;
    const int ib = blockIdx.x, js = blockIdx.y;
    const int i_base = ib * TI, i_warp = i_base + warp * 32;
    const int j0 = js * JRANGE;
    const int r0 = lane >> 2, c0 = (lane & 3) * 2;

    const uint32_t sb = (uint32_t)__cvta_generic_to_shared(smem);

    // adj staging: fully coalesced — chunk q*128+t -> row q*16+(t>>3), seg t&7
    const int arow = t >> 3, aseg = t & 7;
    // Wh staging: chunk q*128+t -> row q*16+(t>>3), seg t&7
    const float* adj_base = adj + (size_t)(i_base + arow) * N + j0 + aseg * 4;
    const __half* wh_base = g_Wh_h + (size_t)(j0 + arow) * 64 + aseg * 8;

#define PREFETCH(tt)                                                           \
    do {                                                                       \
        const uint32_t st_ = sb + ((tt) % 3) * STAGE_B;                        \
        const float* as_ = adj_base + (tt) * TJ;                               \
        _Pragma("unroll")                                                      \
        for (int q_ = 0; q_ < 8; q_++)                                         \
            CP_ASYNC16(st_ + (q_ * 16 + arow) * (ADJ_STR * 4) + aseg * 16,     \
                       as_ + (size_t)(q_ * 16) * N);                           \
        const uint32_t wst_ = st_ + STAGE_ADJ_B;                               \
        const __half* ws_ = wh_base + (size_t)((tt) * TJ) * 64;                \
        CP_ASYNC16(wst_ + arow * 144 + aseg * 16, ws_);                        \
        CP_ASYNC16(wst_ + (16 + arow) * 144 + aseg * 16, ws_ + 16 * 64);       \
        CP_COMMIT();                                                           \
    } while (0)

    // e1 fp16 splats (invariant)
    __half2 e1x2[2][2], e1y2[2][2];
    #pragma unroll
    for (int mt = 0; mt < 2; mt++)
        #pragma unroll
        for (int aa = 0; aa < 2; aa++) {
            float2 e1f = g_E1P[i_warp + mt * 16 + aa * 8 + r0];
            e1x2[mt][aa] = __half2half2(__float2half(e1f.x));
            e1y2[mt][aa] = __half2half2(__float2half(e1f.y));
        }

    float acc[2][8][4];
    float accden[2][4];
    #pragma unroll
    for (int mt = 0; mt < 2; mt++) {
        #pragma unroll
        for (int nt = 0; nt < 8; nt++)
            #pragma unroll
            for (int e = 0; e < 4; e++) acc[mt][nt][e] = 0.f;
        #pragma unroll
        for (int e = 0; e < 4; e++) accden[mt][e] = 0.f;
    }
    const uint32_t bones = (r0 == 0) ? 0x3C003C00u : 0u;   // fp16 ones column

    // ldmatrix lane map (x4.trans)
    const int mm = lane >> 3;
    const int ldsm_row = (mm & 1) * 8 + (lane & 7);
    const int ldsm_f   = mm >> 1;

    PREFETCH(0); PREFETCH(1); PREFETCH(2);

    #pragma unroll 1
    for (int it = 0; it < NT; it++) {
        const int s = it % 3;
        const int jt = j0 + it * TJ;
        CP_WAIT2();
        __syncthreads();

        // ---- e2 fp16 pair loads (L1-hot) ----
        __half2 ex2[2][2], ey2[2][2];
        #pragma unroll
        for (int kt = 0; kt < 2; kt++)
            #pragma unroll
            for (int hh = 0; hh < 2; hh++) {
                const int jj = jt + kt * 16 + hh * 8 + c0;
                ex2[kt][hh] = *(const __half2*)&g_E2XH[jj];
                ey2[kt][hh] = *(const __half2*)&g_E2YH[jj];
            }

        // ---- A fragments (P) from smem adj (conflict-free float2 LDS) ----
        const float* adjS = (const float*)(smem + s * STAGE_B);
        uint32_t afr[2][2][4];
        #pragma unroll
        for (int mt = 0; mt < 2; mt++)
            #pragma unroll
            for (int kt = 0; kt < 2; kt++)
                #pragma unroll
                for (int aa = 0; aa < 2; aa++)
                    #pragma unroll
                    for (int hh = 0; hh < 2; hh++) {
                        const int R = warp * 32 + mt * 16 + aa * 8 + r0;
                        float2 ad = *(const float2*)&adjS[R * ADJ_STR +
                                                          kt * 16 + hh * 8 + c0];
                        __half2 ah = __floats2half2_rn(ad.x, ad.y);
                        __half2 u  = __hmul2(e1x2[mt][aa], ex2[kt][hh]);
                        __half2 v  = __hmul2(e1y2[mt][aa], ey2[kt][hh]);
                        __half2 p  = __hmul2(__hmax2(u, v), ah);
                        afr[mt][kt][aa + 2 * hh] = *(uint32_t*)&p;
                    }

        // ---- B fragments to regs (LDSM from Wh stage s) ----
        uint32_t bq[2][4][4];
        #pragma unroll
        for (int kt = 0; kt < 2; kt++) {
            const uint32_t abase = sb + s * STAGE_B + STAGE_ADJ_B
                                   + (kt * 16 + ldsm_row) * 144 + ldsm_f * 16;
            #pragma unroll
            for (int p = 0; p < 4; p++)
                LDSM_X4_T(bq[kt][p][0], bq[kt][p][1], bq[kt][p][2], bq[kt][p][3],
                          abase + p * 32);
        }
        __syncthreads();   // all warps done with stage s

        // ---- prefetch tile it+3 into stage s ----
        if (it + 3 < NT) { PREFETCH(it + 3); } else { CP_COMMIT(); }

        // ---- MMAs (all operands in registers) ----
        #pragma unroll
        for (int kt = 0; kt < 2; kt++) {
            #pragma unroll
            for (int p = 0; p < 4; p++) {
                MMA_F16(acc[0][2 * p],     afr[0][kt], bq[kt][p][0], bq[kt][p][1]);
                MMA_F16(acc[0][2 * p + 1], afr[0][kt], bq[kt][p][2], bq[kt][p][3]);
                MMA_F16(acc[1][2 * p],     afr[1][kt], bq[kt][p][0], bq[kt][p][1]);
                MMA_F16(acc[1][2 * p + 1], afr[1][kt], bq[kt][p][2], bq[kt][p][3]);
            }
            MMA_F16(accden[0], afr[0][kt], bones, bones);
            MMA_F16(accden[1], afr[1][kt], bones, bones);
        }
    }

    // ---- epilogue ----
    float* ob = g_acc[js];
    #pragma unroll
    for (int mt = 0; mt < 2; mt++) {
        const int ir = i_warp + mt * 16 + r0;
        #pragma unroll
        for (int nt = 0; nt < 8; nt++) {
            const int fc = nt * 8 + c0;
            *(float2*)&ob[(size_t)ir * FOUT + fc] =
                make_float2(acc[mt][nt][0], acc[mt][nt][1]);
            *(float2*)&ob[(size_t)(ir + 8) * FOUT + fc] =
                make_float2(acc[mt][nt][2], acc[mt][nt][3]);
        }
    }
    if ((lane & 3) == 0) {
        #pragma unroll
        for (int mt = 0; mt < 2; mt++) {
            g_den[js][i_warp + mt * 16 + r0]     = accden[mt][0];
            g_den[js][i_warp + mt * 16 + 8 + r0] = accden[mt][2];
        }
    }
}

// ============================================================
// Kernel C: combine partials, normalize, ELU.
// ============================================================
__global__ void __launch_bounds__(256) gat_final(float* __restrict__ out)
{
    const int idx = blockIdx.x * 256 + threadIdx.x;   // < N*FOUT
    const int i = idx >> 6;
    float d = 0.f, v = 0.f;
    #pragma unroll
    for (int s = 0; s < JSPLIT; s++) {
        d += g_den[s][i];
        v += g_acc[s][idx];
    }
    float h = v / d;
    out[idx] = (h > 0.f) ? h : expm1f(h);
}

// ============================================================
extern "C" void kernel_launch(void* const* d_in, const int* in_sizes, int n_in,
                              void* d_out, int out_size)
{
    const float* x   = (const float*)d_in[0];
    const float* adj = (const float*)d_in[1];
    const float* W   = (const float*)d_in[2];
    const float* a   = (const float*)d_in[3];
    float* out = (float*)d_out;

    cudaFuncSetAttribute(gat_prep, cudaFuncAttributeMaxDynamicSharedMemorySize,
                         PREP_SMEM);
    cudaFuncSetAttribute(gat_attn, cudaFuncAttributeMaxDynamicSharedMemorySize,
                         SMEMB_BYTES);

    gat_prep<<<N / 32, 256, PREP_SMEM>>>(x, W, a);
    gat_attn<<<dim3(N / TI, JSPLIT), TI, SMEMB_BYTES>>>(adj);
    gat_final<<<(N * FOUT) / 256, 256>>>(out);
}